// round 15
// baseline (speedup 1.0000x reference)
#include <cuda_runtime.h>

// IDWT (inverse Haar) — read/write temporal batching experiment.
// Inputs: LL, LH, HL, HH each [B=16, C=64, H2=128, W2=128] fp32.
// Output: [16, 64, 256, 256] fp32.
// out[2i,2j]=a, out[2i,2j+1]=b, out[2i+1,2j]=c, out[2i+1,2j+1]=d where
//   a=(LL+LH+HL+HH)/2, b=(LL+LH-HL-HH)/2, c=(LL-LH+HL-HH)/2, d=(LL-LH-HL+HH)/2
//
// Same dense-store float2 layout as the confirmed 80.4us kernel, but each
// thread processes UNROLL=4 groups with ALL 16 loads issued front-batched
// (MLP=16), then computes, then issues all 8 STG.128 back-to-back. Goal:
// longer same-direction DRAM bursts -> less R/W turnaround loss.
// Block covers UNROLL*BLOCK = 2048 contiguous float2 groups; a plane has
// 8192 groups, so blocks never straddle a plane/row-group boundary.

static constexpr int W2 = 128;                   // input width
static constexpr int H2 = 128;                   // input height
static constexpr int W2F2 = W2 / 2;              // float2 groups per input row = 64
static constexpr int OUT_ROW_F4 = (2 * W2) / 4;  // 64 float4 per output row

static constexpr int BLOCK  = 512;
static constexpr int UNROLL = 4;

__global__ void __launch_bounds__(BLOCK) idwt_haar_kernel(
    const float2* __restrict__ ll2,
    const float2* __restrict__ lh2,
    const float2* __restrict__ hl2,
    const float2* __restrict__ hh2,
    float4* __restrict__ out4)
{
    unsigned idx0 = blockIdx.x * (BLOCK * UNROLL) + threadIdx.x;

    // ---- Phase 1: all loads, front-batched (MLP = 16 independent LDG.64) ----
    float2 ll[UNROLL], lh[UNROLL], hl[UNROLL], hh[UNROLL];
#pragma unroll
    for (int k = 0; k < UNROLL; k++) {
        unsigned idx = idx0 + k * BLOCK;
        ll[k] = __ldcs(&ll2[idx]);
        lh[k] = __ldcs(&lh2[idx]);
        hl[k] = __ldcs(&hl2[idx]);
        hh[k] = __ldcs(&hh2[idx]);
    }

    // ---- Phase 2: compute + stores, back-to-back ----
#pragma unroll
    for (int k = 0; k < UNROLL; k++) {
        unsigned idx = idx0 + k * BLOCK;

        float ax, bx, cx, dx, ay, by, cy, dy;
        {
            float s0, s1, d0, d1;
            s0 = ll[k].x + lh[k].x; s1 = hl[k].x + hh[k].x;
            d0 = ll[k].x - lh[k].x; d1 = hl[k].x - hh[k].x;
            ax = 0.5f * (s0 + s1); bx = 0.5f * (s0 - s1);
            cx = 0.5f * (d0 + d1); dx = 0.5f * (d0 - d1);
            s0 = ll[k].y + lh[k].y; s1 = hl[k].y + hh[k].y;
            d0 = ll[k].y - lh[k].y; d1 = hl[k].y - hh[k].y;
            ay = 0.5f * (s0 + s1); by = 0.5f * (s0 - s1);
            cy = 0.5f * (d0 + d1); dy = 0.5f * (d0 - d1);
        }

        // idx = plane*8192 + row*64 + col2
        unsigned col2  = idx & (W2F2 - 1);        // 0..63
        unsigned row   = (idx >> 6) & (H2 - 1);   // 0..127
        unsigned plane = idx >> 13;               // 0..1023

        unsigned base = plane * (2u * H2 * OUT_ROW_F4)
                      + (2u * row) * OUT_ROW_F4
                      + col2;

        __stcs(&out4[base],              make_float4(ax, bx, ay, by));
        __stcs(&out4[base + OUT_ROW_F4], make_float4(cx, dx, cy, dy));
    }
}

extern "C" void kernel_launch(void* const* d_in, const int* in_sizes, int n_in,
                              void* d_out, int out_size)
{
    const float2* ll = (const float2*)d_in[0];
    const float2* lh = (const float2*)d_in[1];
    const float2* hl = (const float2*)d_in[2];
    const float2* hh = (const float2*)d_in[3];
    float4* out = (float4*)d_out;

    int n_groups = in_sizes[0] / 2;                        // 2^23
    int grid = n_groups / (BLOCK * UNROLL);                // 4096
    idwt_haar_kernel<<<grid, BLOCK>>>(ll, lh, hl, hh, out);
}

// round 16
// speedup vs baseline: 1.0004x; 1.0004x over previous
#include <cuda_runtime.h>

// IDWT (inverse Haar) — FINAL (confirmed R12/R13/R14 configuration, reverted
// after the R15 batching experiment regressed per its pre-registered falsifier).
// Inputs: LL, LH, HL, HH each [B=16, C=64, H2=128, W2=128] fp32.
// Output: [16, 64, 256, 256] fp32.
// out[2i,2j]=a, out[2i,2j+1]=b, out[2i+1,2j]=c, out[2i+1,2j+1]=d where
//   a=(LL+LH+HL+HH)/2, b=(LL+LH-HL-HH)/2, c=(LL-LH+HL-HH)/2, d=(LL-LH-HL+HH)/2
//
// One thread per float2 (2 coefficients). Each thread writes exactly one
// float4 into each of two output rows; consecutive lanes hit consecutive
// float4s -> every STG.128 is a dense 512B warp transaction. Touch-once
// traffic -> .cs streaming policy on all loads/stores.
//
// Measured at the mixed-R/W HBM ceiling: ~6.45 TB/s, DRAM ~81%, kernel ~75us.
// Ruled out by isolated A/B tests: v8 STG.256 (neutral), .cs policy (neutral),
// float4 granule (neutral), block 256 vs 512 (noise), persistent single-wave
// launch (regression), unroll-4 load/store temporal batching (regression:
// occ 76->40%, DRAM 81->77%). The DRAM bus with 1:1 read/write turnaround is
// the binding resource; no SM-side pipe exceeds 16% utilization.

static constexpr int W2 = 128;                   // input width
static constexpr int H2 = 128;                   // input height
static constexpr int W2F2 = W2 / 2;              // float2 groups per input row = 64
static constexpr int OUT_ROW_F4 = (2 * W2) / 4;  // 64 float4 per output row

static constexpr int BLOCK = 512;

__global__ void __launch_bounds__(BLOCK) idwt_haar_kernel(
    const float2* __restrict__ ll2,
    const float2* __restrict__ lh2,
    const float2* __restrict__ hl2,
    const float2* __restrict__ hh2,
    float4* __restrict__ out4)
{
    unsigned idx = blockIdx.x * BLOCK + threadIdx.x;   // one per 2 input coeffs

    float2 ll = __ldcs(&ll2[idx]);
    float2 lh = __ldcs(&lh2[idx]);
    float2 hl = __ldcs(&hl2[idx]);
    float2 hh = __ldcs(&hh2[idx]);

    float ax, bx, cx, dx, ay, by, cy, dy;
    {
        float s0, s1, d0, d1;
        s0 = ll.x + lh.x; s1 = hl.x + hh.x; d0 = ll.x - lh.x; d1 = hl.x - hh.x;
        ax = 0.5f * (s0 + s1); bx = 0.5f * (s0 - s1);
        cx = 0.5f * (d0 + d1); dx = 0.5f * (d0 - d1);
        s0 = ll.y + lh.y; s1 = hl.y + hh.y; d0 = ll.y - lh.y; d1 = hl.y - hh.y;
        ay = 0.5f * (s0 + s1); by = 0.5f * (s0 - s1);
        cy = 0.5f * (d0 + d1); dy = 0.5f * (d0 - d1);
    }

    // idx = plane*8192 + row*64 + col2 (col2 in [0,64), row in [0,128), plane in [0,1024)).
    unsigned col2  = idx & (W2F2 - 1);        // 0..63
    unsigned row   = (idx >> 6) & (H2 - 1);   // 0..127
    unsigned plane = idx >> 13;               // 0..1023

    // Output base (float4 units): plane*32768 + (2*row)*64 + col2. Max < 2^25.
    unsigned base = plane * (2u * H2 * OUT_ROW_F4)
                  + (2u * row) * OUT_ROW_F4
                  + col2;

    // Row 2i: [a0,b0,a1,b1]; Row 2i+1: [c0,d0,c1,d1] — one dense float4 each.
    __stcs(&out4[base],              make_float4(ax, bx, ay, by));
    __stcs(&out4[base + OUT_ROW_F4], make_float4(cx, dx, cy, dy));
}

extern "C" void kernel_launch(void* const* d_in, const int* in_sizes, int n_in,
                              void* d_out, int out_size)
{
    const float2* ll = (const float2*)d_in[0];
    const float2* lh = (const float2*)d_in[1];
    const float2* hl = (const float2*)d_in[2];
    const float2* hh = (const float2*)d_in[3];
    float4* out = (float4*)d_out;

    int n_groups = in_sizes[0] / 2;              // 2^23
    int grid = (n_groups + BLOCK - 1) / BLOCK;   // 16384
    idwt_haar_kernel<<<grid, BLOCK>>>(ll, lh, hl, hh, out);
}